// round 16
// baseline (speedup 1.0000x reference)
#include <cuda_runtime.h>
#include <cuda_bf16.h>
#include <mma.h>
#include <math.h>
#include <stdint.h>

using namespace nvcuda;

#define NROWS 8192
#define DDIM  512
#define NQKV  1536
#define NG    64
#define MAXG  512
#define GPAD  256
#define SCALE 0.044194173824159216f   // 1/sqrt(512)

// ---------------------------------------------------------------------------
// Scratch (device globals: allocation-free rule)
// ---------------------------------------------------------------------------
__device__ float g_S[(size_t)NG * MAXG * MAXG];      // scores, then packed P
__device__ __nv_bfloat16 g_xh[NROWS * DDIM];         // A operand hi (x, then att)
__device__ __nv_bfloat16 g_xl[NROWS * DDIM];         // A operand lo
__device__ __nv_bfloat16 g_pwh[DDIM * NQKV];         // packed Wq|Wk|Wv hi
__device__ __nv_bfloat16 g_pwl[DDIM * NQKV];
__device__ __nv_bfloat16 g_owh[DDIM * DDIM];         // Wo hi
__device__ __nv_bfloat16 g_owl[DDIM * DDIM];
// compacted per-group bf16-split q/k/v: [NG][GPAD][DDIM]
__device__ __nv_bfloat16 g_qch[(size_t)NG * GPAD * DDIM];
__device__ __nv_bfloat16 g_qcl[(size_t)NG * GPAD * DDIM];
__device__ __nv_bfloat16 g_kch[(size_t)NG * GPAD * DDIM];
__device__ __nv_bfloat16 g_kcl[(size_t)NG * GPAD * DDIM];
__device__ __nv_bfloat16 g_vch[(size_t)NG * GPAD * DDIM];
__device__ __nv_bfloat16 g_vcl[(size_t)NG * GPAD * DDIM];
__device__ float g_btq[16 * NQKV];                   // broadcast bias tiles
__device__ float g_bto[16 * DDIM];
__device__ int   g_cnt[NG];
__device__ int   g_mem[NG * MAXG];
__device__ int   g_pos[NROWS];

__device__ __forceinline__ void bsplit(float v, __nv_bfloat16& h, __nv_bfloat16& l) {
    h = __float2bfloat16(v);
    l = __float2bfloat16(v - __bfloat162float(h));
}

__device__ __forceinline__ uint32_t smem_u32(const void* p) {
    uint32_t a;
    asm("{ .reg .u64 t; cvta.to.shared.u64 t, %1; cvt.u32.u64 %0, t; }"
        : "=r"(a) : "l"(p));
    return a;
}

__device__ __forceinline__ void cp16(void* sdst, const void* gsrc) {
    asm volatile("cp.async.cg.shared.global [%0], [%1], 16;"
                 :: "r"(smem_u32(sdst)), "l"(gsrc));
}
#define CP_COMMIT() asm volatile("cp.async.commit_group;" ::: "memory")
template <int N>
__device__ __forceinline__ void cp_wait() {
    asm volatile("cp.async.wait_group %0;" :: "n"(N) : "memory");
}

// ---------------------------------------------------------------------------
// Small kernels
// ---------------------------------------------------------------------------
__global__ void build_groups_kernel(const int* __restrict__ labels) {
    int i = blockIdx.x * blockDim.x + threadIdx.x;
    if (i < NROWS) {
        int lb = labels[i];
        if (lb >= 0) {
            int pos = atomicAdd(&g_cnt[lb], 1);
            if (pos < MAXG) g_mem[lb * MAXG + pos] = i;
            g_pos[i] = pos;
        }
    }
}

// Fused prep:
//  [0, 4096)     : split x
//  [4096, 8192)  : pack weights (Wq scaled)
//  [8192, 8320)  : bias tiles (bq scaled)
__global__ void prep_kernel(const float* __restrict__ x,
                            const float* __restrict__ Wq,
                            const float* __restrict__ Wk,
                            const float* __restrict__ Wv,
                            const float* __restrict__ Wo,
                            const float* __restrict__ bq,
                            const float* __restrict__ bk,
                            const float* __restrict__ bv,
                            const float* __restrict__ bo) {
    const int b = blockIdx.x;
    const int tid = threadIdx.x;
    if (b < 4096) {
        int i = b * 256 + tid;
        float4 f = ((const float4*)x)[i];
        __nv_bfloat16 h0, h1, h2, h3, l0, l1, l2, l3;
        bsplit(f.x, h0, l0); bsplit(f.y, h1, l1);
        bsplit(f.z, h2, l2); bsplit(f.w, h3, l3);
        __nv_bfloat162* ph = (__nv_bfloat162*)g_xh;
        __nv_bfloat162* pl = (__nv_bfloat162*)g_xl;
        ph[i * 2 + 0] = __nv_bfloat162(h0, h1);
        ph[i * 2 + 1] = __nv_bfloat162(h2, h3);
        pl[i * 2 + 0] = __nv_bfloat162(l0, l1);
        pl[i * 2 + 1] = __nv_bfloat162(l2, l3);
    } else if (b < 8192) {
        int i = (b - 4096) * 256 + tid;
        int w = i >> 18;
        int r = i & 262143;
        const float* W = (w == 0) ? Wq : (w == 1) ? Wk : (w == 2) ? Wv : Wo;
        float v = W[r];
        if (w == 0) v *= SCALE;
        __nv_bfloat16 h, l;
        bsplit(v, h, l);
        if (w < 3) {
            int k = r >> 9, n = r & 511;
            size_t o = (size_t)k * NQKV + w * 512 + n;
            g_pwh[o] = h; g_pwl[o] = l;
        } else {
            g_owh[r] = h; g_owl[r] = l;
        }
    } else {
        int i = (b - 8192) * 256 + tid;
        int row = i >> 11;
        int col = i & 2047;
        if (col < NQKV) {
            int w = col >> 9, c = col & 511;
            g_btq[row * NQKV + col] =
                (w == 0) ? bq[c] * SCALE : (w == 1) ? bk[c] : bv[c];
        } else {
            int c = col - NQKV;
            g_bto[row * DDIM + c] = bo[c];
        }
    }
}

// Zero att-split rows for invalid labels
__global__ void zero_invalid_kernel(const int* __restrict__ labels) {
    int i = blockIdx.x * blockDim.x + threadIdx.x;
    int row = i >> 6, c = i & 63;
    if (labels[row] < 0) {
        uint4 z = make_uint4(0, 0, 0, 0);
        ((uint4*)g_xh)[(size_t)row * 64 + c] = z;
        ((uint4*)g_xl)[(size_t)row * 64 + c] = z;
    }
}

// ---------------------------------------------------------------------------
// GEMM common constants (proven R11 pipeline)
// ---------------------------------------------------------------------------
#define KC    32
#define LDA_S 48
#define LDB_S 144

#define OFF_AH 0
#define OFF_AL (128 * LDA_S * 2)
#define OFF_BH (2 * 128 * LDA_S * 2)
#define OFF_BL (2 * 128 * LDA_S * 2 + KC * LDB_S * 2)
#define STAGE_BYTES (2 * 128 * LDA_S * 2 + 2 * KC * LDB_S * 2)  // 43008
#define GEMM_SMEM (2 * STAGE_BYTES)                             // 86016

// ---------------------------------------------------------------------------
// QKV GEMM: C = x @ [Wq|Wk|Wv] + bias; epilogue scatters compacted bf16 split
// grid (NQKV/128=12, 64), block 256.
// ---------------------------------------------------------------------------
__global__ __launch_bounds__(256, 2)
void qkv_gemm_kernel(const int* __restrict__ labels) {
    extern __shared__ char smem[];
    const __nv_bfloat16* Ah = g_xh;
    const __nv_bfloat16* Al = g_xl;

    const int tid = threadIdx.x;
    const int wid = tid >> 5;
    const int wRow = (wid & 1) * 64;
    const int wCol = (wid >> 1) * 32;
    const int rowBase = blockIdx.y * 128;
    const int colBase = blockIdx.x * 128;

    const int ar0 = (tid * 2) >> 2,       ac0 = ((tid * 2) & 3) * 8;
    const int ar1 = (tid * 2 + 1) >> 2,   ac1 = ((tid * 2 + 1) & 3) * 8;
    const int br0 = (tid * 2) >> 4,       bc0 = ((tid * 2) & 15) * 8;
    const int br1 = (tid * 2 + 1) >> 4,   bc1 = ((tid * 2 + 1) & 15) * 8;

    auto prefetch = [&](int it, int s) {
        char* st = smem + s * STAGE_BYTES;
        const int kc = it * KC;
        __nv_bfloat16* sAh = (__nv_bfloat16*)(st + OFF_AH);
        __nv_bfloat16* sAl = (__nv_bfloat16*)(st + OFF_AL);
        __nv_bfloat16* sBh = (__nv_bfloat16*)(st + OFF_BH);
        __nv_bfloat16* sBl = (__nv_bfloat16*)(st + OFF_BL);
        size_t ga0 = (size_t)(rowBase + ar0) * DDIM + kc + ac0;
        size_t ga1 = (size_t)(rowBase + ar1) * DDIM + kc + ac1;
        cp16(&sAh[ar0 * LDA_S + ac0], Ah + ga0);
        cp16(&sAh[ar1 * LDA_S + ac1], Ah + ga1);
        cp16(&sAl[ar0 * LDA_S + ac0], Al + ga0);
        cp16(&sAl[ar1 * LDA_S + ac1], Al + ga1);
        size_t gb0 = (size_t)(kc + br0) * NQKV + colBase + bc0;
        size_t gb1 = (size_t)(kc + br1) * NQKV + colBase + bc1;
        cp16(&sBh[br0 * LDB_S + bc0], g_pwh + gb0);
        cp16(&sBh[br1 * LDB_S + bc1], g_pwh + gb1);
        cp16(&sBl[br0 * LDB_S + bc0], g_pwl + gb0);
        cp16(&sBl[br1 * LDB_S + bc1], g_pwl + gb1);
    };

    wmma::fragment<wmma::accumulator, 16, 16, 16, float> acc[4][2];
#pragma unroll
    for (int mi = 0; mi < 4; mi++)
#pragma unroll
        for (int ni = 0; ni < 2; ni++)
            wmma::load_matrix_sync(acc[mi][ni],
                                   g_btq + (colBase + wCol + ni * 16),
                                   NQKV, wmma::mem_row_major);

    const int NIT = DDIM / KC;
    prefetch(0, 0);
    CP_COMMIT();

    for (int it = 0; it < NIT; it++) {
        const int cur = it & 1;
        if (it + 1 < NIT) {
            prefetch(it + 1, cur ^ 1);
            CP_COMMIT();
            cp_wait<1>();
        } else {
            cp_wait<0>();
        }
        __syncthreads();

        char* st = smem + cur * STAGE_BYTES;
        __nv_bfloat16* sAh = (__nv_bfloat16*)(st + OFF_AH);
        __nv_bfloat16* sAl = (__nv_bfloat16*)(st + OFF_AL);
        __nv_bfloat16* sBh = (__nv_bfloat16*)(st + OFF_BH);
        __nv_bfloat16* sBl = (__nv_bfloat16*)(st + OFF_BL);

#pragma unroll
        for (int k16 = 0; k16 < KC; k16 += 16) {
            wmma::fragment<wmma::matrix_a, 16, 16, 16, __nv_bfloat16, wmma::row_major> ah[4], al[4];
            wmma::fragment<wmma::matrix_b, 16, 16, 16, __nv_bfloat16, wmma::row_major> bh[2], bl[2];
#pragma unroll
            for (int mi = 0; mi < 4; mi++) {
                wmma::load_matrix_sync(ah[mi], &sAh[(wRow + mi * 16) * LDA_S + k16], LDA_S);
                wmma::load_matrix_sync(al[mi], &sAl[(wRow + mi * 16) * LDA_S + k16], LDA_S);
            }
#pragma unroll
            for (int ni = 0; ni < 2; ni++) {
                wmma::load_matrix_sync(bh[ni], &sBh[k16 * LDB_S + wCol + ni * 16], LDB_S);
                wmma::load_matrix_sync(bl[ni], &sBl[k16 * LDB_S + wCol + ni * 16], LDB_S);
            }
#pragma unroll
            for (int mi = 0; mi < 4; mi++)
#pragma unroll
                for (int ni = 0; ni < 2; ni++) {
                    wmma::mma_sync(acc[mi][ni], ah[mi], bh[ni], acc[mi][ni]);
                    wmma::mma_sync(acc[mi][ni], ah[mi], bl[ni], acc[mi][ni]);
                    wmma::mma_sync(acc[mi][ni], al[mi], bh[ni], acc[mi][ni]);
                }
        }
        __syncthreads();
    }

    // epilogue: stage tile in smem, then scatter compacted bf16 split
    float* so = (float*)smem;   // 128 x 132
#pragma unroll
    for (int mi = 0; mi < 4; mi++)
#pragma unroll
        for (int ni = 0; ni < 2; ni++)
            wmma::store_matrix_sync(&so[(wRow + mi * 16) * 132 + wCol + ni * 16],
                                    acc[mi][ni], 132, wmma::mem_row_major);
    __syncthreads();

    const int buf = colBase >> 9;          // 0=q, 1=k, 2=v
    const int colIn = colBase & 511;
    __nv_bfloat16* dH = (buf == 0) ? g_qch : (buf == 1) ? g_kch : g_vch;
    __nv_bfloat16* dL = (buf == 0) ? g_qcl : (buf == 1) ? g_kcl : g_vcl;

    for (int t = tid; t < 4096; t += 256) {
        int r = t >> 5, c4 = (t & 31) << 2;    // 128 rows x 32 float4-cols
        int gr = rowBase + r;
        int lb = labels[gr];
        if (lb < 0) continue;
        int pos = g_pos[gr];
        if (pos >= GPAD) continue;
        float4 f = *(float4*)&so[r * 132 + c4];
        __nv_bfloat16 h0, h1, h2, h3, l0, l1, l2, l3;
        bsplit(f.x, h0, l0); bsplit(f.y, h1, l1);
        bsplit(f.z, h2, l2); bsplit(f.w, h3, l3);
        size_t o = (((size_t)lb * GPAD + pos) * DDIM + colIn + c4) >> 1;
        ((__nv_bfloat162*)dH)[o]     = __nv_bfloat162(h0, h1);
        ((__nv_bfloat162*)dH)[o + 1] = __nv_bfloat162(h2, h3);
        ((__nv_bfloat162*)dL)[o]     = __nv_bfloat162(l0, l1);
        ((__nv_bfloat162*)dL)[o + 1] = __nv_bfloat162(l2, l3);
    }
}

// ---------------------------------------------------------------------------
// Output GEMM: out = att @ Wo + bias (direct fp32 store) — proven R11 kernel
// ---------------------------------------------------------------------------
__global__ __launch_bounds__(256, 2)
void out_gemm_kernel(float* __restrict__ C) {
    extern __shared__ char smem[];
    const __nv_bfloat16* Ah = g_xh;
    const __nv_bfloat16* Al = g_xl;

    const int tid = threadIdx.x;
    const int wid = tid >> 5;
    const int wRow = (wid & 1) * 64;
    const int wCol = (wid >> 1) * 32;
    const int rowBase = blockIdx.y * 128;
    const int colBase = blockIdx.x * 128;

    const int ar0 = (tid * 2) >> 2,       ac0 = ((tid * 2) & 3) * 8;
    const int ar1 = (tid * 2 + 1) >> 2,   ac1 = ((tid * 2 + 1) & 3) * 8;
    const int br0 = (tid * 2) >> 4,       bc0 = ((tid * 2) & 15) * 8;
    const int br1 = (tid * 2 + 1) >> 4,   bc1 = ((tid * 2 + 1) & 15) * 8;

    auto prefetch = [&](int it, int s) {
        char* st = smem + s * STAGE_BYTES;
        const int kc = it * KC;
        __nv_bfloat16* sAh = (__nv_bfloat16*)(st + OFF_AH);
        __nv_bfloat16* sAl = (__nv_bfloat16*)(st + OFF_AL);
        __nv_bfloat16* sBh = (__nv_bfloat16*)(st + OFF_BH);
        __nv_bfloat16* sBl = (__nv_bfloat16*)(st + OFF_BL);
        size_t ga0 = (size_t)(rowBase + ar0) * DDIM + kc + ac0;
        size_t ga1 = (size_t)(rowBase + ar1) * DDIM + kc + ac1;
        cp16(&sAh[ar0 * LDA_S + ac0], Ah + ga0);
        cp16(&sAh[ar1 * LDA_S + ac1], Ah + ga1);
        cp16(&sAl[ar0 * LDA_S + ac0], Al + ga0);
        cp16(&sAl[ar1 * LDA_S + ac1], Al + ga1);
        size_t gb0 = (size_t)(kc + br0) * DDIM + colBase + bc0;
        size_t gb1 = (size_t)(kc + br1) * DDIM + colBase + bc1;
        cp16(&sBh[br0 * LDB_S + bc0], g_owh + gb0);
        cp16(&sBh[br1 * LDB_S + bc1], g_owh + gb1);
        cp16(&sBl[br0 * LDB_S + bc0], g_owl + gb0);
        cp16(&sBl[br1 * LDB_S + bc1], g_owl + gb1);
    };

    wmma::fragment<wmma::accumulator, 16, 16, 16, float> acc[4][2];
#pragma unroll
    for (int mi = 0; mi < 4; mi++)
#pragma unroll
        for (int ni = 0; ni < 2; ni++)
            wmma::load_matrix_sync(acc[mi][ni],
                                   g_bto + (colBase + wCol + ni * 16),
                                   DDIM, wmma::mem_row_major);

    const int NIT = DDIM / KC;
    prefetch(0, 0);
    CP_COMMIT();

    for (int it = 0; it < NIT; it++) {
        const int cur = it & 1;
        if (it + 1 < NIT) {
            prefetch(it + 1, cur ^ 1);
            CP_COMMIT();
            cp_wait<1>();
        } else {
            cp_wait<0>();
        }
        __syncthreads();

        char* st = smem + cur * STAGE_BYTES;
        __nv_bfloat16* sAh = (__nv_bfloat16*)(st + OFF_AH);
        __nv_bfloat16* sAl = (__nv_bfloat16*)(st + OFF_AL);
        __nv_bfloat16* sBh = (__nv_bfloat16*)(st + OFF_BH);
        __nv_bfloat16* sBl = (__nv_bfloat16*)(st + OFF_BL);

#pragma unroll
        for (int k16 = 0; k16 < KC; k16 += 16) {
            wmma::fragment<wmma::matrix_a, 16, 16, 16, __nv_bfloat16, wmma::row_major> ah[4], al[4];
            wmma::fragment<wmma::matrix_b, 16, 16, 16, __nv_bfloat16, wmma::row_major> bh[2], bl[2];
#pragma unroll
            for (int mi = 0; mi < 4; mi++) {
                wmma::load_matrix_sync(ah[mi], &sAh[(wRow + mi * 16) * LDA_S + k16], LDA_S);
                wmma::load_matrix_sync(al[mi], &sAl[(wRow + mi * 16) * LDA_S + k16], LDA_S);
            }
#pragma unroll
            for (int ni = 0; ni < 2; ni++) {
                wmma::load_matrix_sync(bh[ni], &sBh[k16 * LDB_S + wCol + ni * 16], LDB_S);
                wmma::load_matrix_sync(bl[ni], &sBl[k16 * LDB_S + wCol + ni * 16], LDB_S);
            }
#pragma unroll
            for (int mi = 0; mi < 4; mi++)
#pragma unroll
                for (int ni = 0; ni < 2; ni++) {
                    wmma::mma_sync(acc[mi][ni], ah[mi], bh[ni], acc[mi][ni]);
                    wmma::mma_sync(acc[mi][ni], ah[mi], bl[ni], acc[mi][ni]);
                    wmma::mma_sync(acc[mi][ni], al[mi], bh[ni], acc[mi][ni]);
                }
        }
        __syncthreads();
    }

#pragma unroll
    for (int mi = 0; mi < 4; mi++)
#pragma unroll
        for (int ni = 0; ni < 2; ni++)
            wmma::store_matrix_sync(
                &C[(size_t)(rowBase + wRow + mi * 16) * DDIM + colBase + wCol + ni * 16],
                acc[mi][ni], DDIM, wmma::mem_row_major);
}

// ---------------------------------------------------------------------------
// Phase 1: scores, 128x128 tiles from compacted bf16, cp.async pipelined.
// grid (NG, 2, 2), block 256 (8 warps 2x4, 64x32 warp tiles).
// ---------------------------------------------------------------------------
#define SC_PL    (128 * LDA_S * 2)       // one plane per stage: 12288 B
#define SC_STAGE (4 * SC_PL)             // Qh,Ql,Kh,Kl: 49152 B
#define SC_SMEM  (2 * SC_STAGE)          // 98304 B

__global__ __launch_bounds__(256, 2)
void scores_kernel() {
    const int g = blockIdx.x, qt = blockIdx.y, kt = blockIdx.z;
    const int m = min(g_cnt[g], GPAD);
    if (qt * 128 >= m || kt * 128 >= m) return;

    extern __shared__ char smem[];
    const int tid = threadIdx.x;
    const int wid = tid >> 5;
    const int wRow = (wid & 1) * 64;
    const int wCol = (wid >> 1) * 32;

    const int ar0 = (tid * 2) >> 2,       ac0 = ((tid * 2) & 3) * 8;
    const int ar1 = (tid * 2 + 1) >> 2,   ac1 = ((tid * 2 + 1) & 3) * 8;

    const size_t qb = ((size_t)g * GPAD + qt * 128) * DDIM;
    const size_t kb = ((size_t)g * GPAD + kt * 128) * DDIM;

    auto prefetch = [&](int it, int s) {
        char* st = smem + s * SC_STAGE;
        const int kc = it * KC;
        __nv_bfloat16* sQh = (__nv_bfloat16*)(st);
        __nv_bfloat16* sQl = (__nv_bfloat16*)(st + SC_PL);
        __nv_bfloat16* sKh = (__nv_bfloat16*)(st + 2 * SC_PL);
        __nv_bfloat16* sKl = (__nv_bfloat16*)(st + 3 * SC_PL);
        size_t q0 = qb + (size_t)ar0 * DDIM + kc + ac0;
        size_t q1 = qb + (size_t)ar1 * DDIM + kc + ac1;
        size_t k0 = kb + (size_t)ar0 * DDIM + kc + ac0;
        size_t k1 = kb + (size_t)ar1 * DDIM + kc + ac1;
        cp16(&sQh[ar0 * LDA_S + ac0], g_qch + q0);
        cp16(&sQh[ar1 * LDA_S + ac1], g_qch + q1);
        cp16(&sQl[ar0 * LDA_S + ac0], g_qcl + q0);
        cp16(&sQl[ar1 * LDA_S + ac1], g_qcl + q1);
        cp16(&sKh[ar0 * LDA_S + ac0], g_kch + k0);
        cp16(&sKh[ar1 * LDA_S + ac1], g_kch + k1);
        cp16(&sKl[ar0 * LDA_S + ac0], g_kcl + k0);
        cp16(&sKl[ar1 * LDA_S + ac1], g_kcl + k1);
    };

    wmma::fragment<wmma::accumulator, 16, 16, 16, float> acc[4][2];
#pragma unroll
    for (int mi = 0; mi < 4; mi++)
#pragma unroll
        for (int ni = 0; ni < 2; ni++)
            wmma::fill_fragment(acc[mi][ni], 0.f);

    const int NIT = DDIM / KC;
    prefetch(0, 0);
    CP_COMMIT();

    for (int it = 0; it < NIT; it++) {
        const int cur = it & 1;
        if (it + 1 < NIT) {
            prefetch(it + 1, cur ^ 1);
            CP_COMMIT();
            cp_wait<1>();
        } else {
            cp_wait<0>();
        }
        __syncthreads();

        char* st = smem + cur * SC_STAGE;
        __nv_bfloat16* sQh = (__nv_bfloat16*)(st);
        __nv_bfloat16* sQl = (__nv_bfloat16*)(st + SC_PL);
        __nv_bfloat16* sKh = (__nv_bfloat16*)(st + 2 * SC_PL);
        __nv_bfloat16* sKl = (__nv_bfloat16*)(st + 3 * SC_PL);

#pragma unroll
        for (int k16 = 0; k16 < KC; k16 += 16) {
            wmma::fragment<wmma::matrix_a, 16, 16, 16, __nv_bfloat16, wmma::row_major> ah[4], al[4];
            wmma::fragment<wmma::matrix_b, 16, 16, 16, __nv_bfloat16, wmma::col_major> bh[2], bl[2];
#pragma unroll
            for (int mi = 0; mi < 4; mi++) {
                wmma::load_matrix_sync(ah[mi], &sQh[(wRow + mi * 16) * LDA_S + k16], LDA_S);
                wmma::load_matrix_sync(al[mi], &sQl[(wRow + mi * 16) * LDA_S + k16], LDA_S);
            }
#pragma unroll
            for (int ni = 0; ni < 2; ni++) {
                wmma::load_matrix_sync(bh[ni], &sKh[(wCol + ni * 16) * LDA_S + k16], LDA_S);
                wmma::load_matrix_sync(bl[ni], &sKl[(wCol + ni * 16) * LDA_S + k16], LDA_S);
            }
#pragma unroll
            for (int mi = 0; mi < 4; mi++)
#pragma unroll
                for (int ni = 0; ni < 2; ni++) {
                    wmma::mma_sync(acc[mi][ni], ah[mi], bh[ni], acc[mi][ni]);
                    wmma::mma_sync(acc[mi][ni], ah[mi], bl[ni], acc[mi][ni]);
                    wmma::mma_sync(acc[mi][ni], al[mi], bh[ni], acc[mi][ni]);
                }
        }
        __syncthreads();
    }

#pragma unroll
    for (int mi = 0; mi < 4; mi++)
#pragma unroll
        for (int ni = 0; ni < 2; ni++)
            wmma::store_matrix_sync(
                &g_S[((size_t)g * MAXG + qt * 128 + wRow + mi * 16) * MAXG
                     + kt * 128 + wCol + ni * 16],
                acc[mi][ni], MAXG, wmma::mem_row_major);
}

// ---------------------------------------------------------------------------
// Phase 2: softmax (scores pre-scaled); P packed bf16 in place
// ---------------------------------------------------------------------------
__global__ __launch_bounds__(256)
void softmax_kernel() {
    const int g = blockIdx.x;
    const int m = min(g_cnt[g], GPAD);
    const int wid = threadIdx.x >> 5, lane = threadIdx.x & 31;
    const int i = blockIdx.y * 8 + wid;
    if (i >= m) return;
    float* rowp = &g_S[((size_t)g * MAXG + i) * MAXG];

    float vals[8];
    const int nt = (m + 31) >> 5;
    float mx = -1e30f;
    for (int t = 0; t < nt; t++) {
        int j = lane + t * 32;
        float v = (j < m) ? rowp[j] : -1e30f;
        vals[t] = v;
        mx = fmaxf(mx, v);
    }
#pragma unroll
    for (int o = 16; o; o >>= 1) mx = fmaxf(mx, __shfl_xor_sync(0xffffffffu, mx, o));
    float sum = 0.f;
    for (int t = 0; t < nt; t++) {
        int j = lane + t * 32;
        float e = (j < m) ? __expf(vals[t] - mx) : 0.f;
        vals[t] = e;
        sum += e;
    }
#pragma unroll
    for (int o = 16; o; o >>= 1) sum += __shfl_xor_sync(0xffffffffu, sum, o);
    float inv = 1.f / sum;
    for (int t = 0; t < nt; t++) {
        int j = lane + t * 32;
        if (j < m) {
            float p = vals[t] * inv;
            __nv_bfloat16 h, l;
            bsplit(p, h, l);
            unsigned u = (unsigned)__bfloat16_as_ushort(h)
                       | ((unsigned)__bfloat16_as_ushort(l) << 16);
            ((unsigned*)rowp)[j] = u;
        }
    }
}

// ---------------------------------------------------------------------------
// Phase 3: out = P @ V_g (V from compacted bf16), scatter+split to g_xh/g_xl.
// grid (NG, 2, 4), block 256.
// ---------------------------------------------------------------------------
#define PLD 72
#define VLD 136

__global__ __launch_bounds__(256)
void pv_kernel() {
    const int g = blockIdx.x, qt = blockIdx.y, nt = blockIdx.z;
    const int m = min(g_cnt[g], GPAD);
    if (qt * 128 >= m) return;
    const int* mem = &g_mem[g * MAXG];
    const int nbase = nt * 128;

    extern __shared__ __nv_bfloat16 sm2[];
    __nv_bfloat16* sPh = sm2;
    __nv_bfloat16* sPl = sm2 + 128 * PLD;
    __nv_bfloat16* sVh = sm2 + 2 * 128 * PLD;
    __nv_bfloat16* sVl = sVh + 64 * VLD;

    const int tid = threadIdx.x;
    const int wid = tid >> 5;
    const int wRow = (wid & 1) * 64;
    const int wCol = (wid >> 1) * 32;

    wmma::fragment<wmma::accumulator, 16, 16, 16, float> acc[4][2];
#pragma unroll
    for (int mi = 0; mi < 4; mi++)
#pragma unroll
        for (int ni = 0; ni < 2; ni++)
            wmma::fill_fragment(acc[mi][ni], 0.f);

    const int JT = (m + 63) >> 6;
    for (int jc = 0; jc < JT; jc++) {
        const int j0 = jc * 64;
        // P tile 128x64 from packed g_S
        for (int t = tid; t < 8192; t += 256) {
            int r = t >> 6, c = t & 63;
            int j = j0 + c;
            unsigned u = 0;
            if (j < m)
                u = *(const unsigned*)&g_S[((size_t)g * MAXG + qt * 128 + r) * MAXG + j];
            sPh[r * PLD + c] = __ushort_as_bfloat16((unsigned short)(u & 0xffffu));
            sPl[r * PLD + c] = __ushort_as_bfloat16((unsigned short)(u >> 16));
        }
        // V tile 64x128 from compacted bf16 (zero pad rows)
        for (int t = tid; t < 1024; t += 256) {
            int r = t >> 4, ch = (t & 15) * 8;
            int j = j0 + r;
            uint4 vh = make_uint4(0, 0, 0, 0), vl = vh;
            if (j < m) {
                size_t o = ((size_t)g * GPAD + j) * DDIM + nbase + ch;
                vh = *(const uint4*)(g_vch + o);
                vl = *(const uint4*)(g_vcl + o);
            }
            *(uint4*)&sVh[r * VLD + ch] = vh;
            *(uint4*)&sVl[r * VLD + ch] = vl;
        }
        __syncthreads();

#pragma unroll
        for (int k16 = 0; k16 < 64; k16 += 16) {
            wmma::fragment<wmma::matrix_a, 16, 16, 16, __nv_bfloat16, wmma::row_major> ah[4], al[4];
            wmma::fragment<wmma::matrix_b, 16, 16, 16, __nv_bfloat16, wmma::row_major> bh[2], bl[2];
#pragma unroll
            for (int mi = 0; mi < 4; mi++) {
                wmma::load_matrix_sync(ah[mi], &sPh[(wRow + mi * 16) * PLD + k16], PLD);
                wmma::load_matrix_sync(al[mi], &sPl[(wRow + mi * 16) * PLD + k16], PLD);
            }
#pragma unroll
            for (int ni = 0; ni < 2; ni++) {
                wmma::load_matrix_sync(bh[ni], &sVh[k16 * VLD + wCol + ni * 16], VLD);
                wmma::load_matrix_sync(bl[ni], &sVl[k16 * VLD + wCol + ni * 16], VLD);
            }
#pragma unroll
            for (int mi = 0; mi < 4; mi++)
#pragma unroll
                for (int ni = 0; ni < 2; ni++) {
                    wmma::mma_sync(acc[mi][ni], ah[mi], bh[ni], acc[mi][ni]);
                    wmma::mma_sync(acc[mi][ni], ah[mi], bl[ni], acc[mi][ni]);
                    wmma::mma_sync(acc[mi][ni], al[mi], bh[ni], acc[mi][ni]);
                }
        }
        __syncthreads();
    }

    float* so = (float*)sm2;   // 128 x 132
#pragma unroll
    for (int mi = 0; mi < 4; mi++)
#pragma unroll
        for (int ni = 0; ni < 2; ni++)
            wmma::store_matrix_sync(&so[(wRow + mi * 16) * 132 + wCol + ni * 16],
                                    acc[mi][ni], 132, wmma::mem_row_major);
    __syncthreads();

    for (int t = tid; t < 4096; t += 256) {
        int r = t >> 5, c4 = (t & 31) << 2;
        int i = qt * 128 + r;
        if (i < m) {
            int row = mem[i];
            float4 f = *(float4*)&so[r * 132 + c4];
            __nv_bfloat16 h0, h1, h2, h3, l0, l1, l2, l3;
            bsplit(f.x, h0, l0); bsplit(f.y, h1, l1);
            bsplit(f.z, h2, l2); bsplit(f.w, h3, l3);
            size_t o = ((size_t)row * DDIM + nbase + c4) >> 1;
            ((__nv_bfloat162*)g_xh)[o]     = __nv_bfloat162(h0, h1);
            ((__nv_bfloat162*)g_xh)[o + 1] = __nv_bfloat162(h2, h3);
            ((__nv_bfloat162*)g_xl)[o]     = __nv_bfloat162(l0, l1);
            ((__nv_bfloat162*)g_xl)[o + 1] = __nv_bfloat162(l2, l3);
        }
    }
}

// ---------------------------------------------------------------------------
// Launch
// ---------------------------------------------------------------------------
extern "C" void kernel_launch(void* const* d_in, const int* in_sizes, int n_in,
                              void* d_out, int out_size) {
    const float* x      = (const float*)d_in[0];
    const int*   labels = (const int*)  d_in[1];
    const float* Wq     = (const float*)d_in[2];
    const float* bq     = (const float*)d_in[3];
    const float* Wk     = (const float*)d_in[4];
    const float* bk     = (const float*)d_in[5];
    const float* Wv     = (const float*)d_in[6];
    const float* bv     = (const float*)d_in[7];
    const float* Wo     = (const float*)d_in[8];
    const float* bo     = (const float*)d_in[9];
    float* out = (float*)d_out;

    void* cntp;
    cudaGetSymbolAddress(&cntp, g_cnt);

    const int pv_smem = (2 * 128 * PLD + 2 * 64 * VLD) * (int)sizeof(__nv_bfloat16); // 71680
    cudaFuncSetAttribute(scores_kernel, cudaFuncAttributeMaxDynamicSharedMemorySize, SC_SMEM);
    cudaFuncSetAttribute(pv_kernel, cudaFuncAttributeMaxDynamicSharedMemorySize, pv_smem);
    cudaFuncSetAttribute(qkv_gemm_kernel, cudaFuncAttributeMaxDynamicSharedMemorySize, GEMM_SMEM);
    cudaFuncSetAttribute(out_gemm_kernel, cudaFuncAttributeMaxDynamicSharedMemorySize, GEMM_SMEM);

    cudaMemsetAsync(cntp, 0, NG * sizeof(int));
    build_groups_kernel<<<NROWS / 256, 256>>>(labels);
    prep_kernel<<<8320, 256>>>(x, Wq, Wk, Wv, Wo, bq, bk, bv, bo);

    qkv_gemm_kernel<<<dim3(NQKV / 128, NROWS / 128), 256, GEMM_SMEM>>>(labels);

    scores_kernel<<<dim3(NG, 2, 2), 256, SC_SMEM>>>();
    softmax_kernel<<<dim3(NG, 32), 256>>>();
    zero_invalid_kernel<<<(NROWS * 64) / 256, 256>>>(labels);
    pv_kernel<<<dim3(NG, 2, 4), 256, pv_smem>>>();

    out_gemm_kernel<<<dim3(DDIM / 128, NROWS / 128), 256, GEMM_SMEM>>>(out);
}